// round 3
// baseline (speedup 1.0000x reference)
#include <cuda_runtime.h>
#include <math.h>

// ---------------- problem constants ----------------
#define NB   8
#define CINC 512
#define HFD  60
#define SP   3600            // 60*60
#define NC   19
#define HIR  480

// x out:  8*19*480*480 = 35020800 ; attentions: 8*19*2304*36 = 12607488
#define XOUT_ELEMS  35020800
#define ATT_ELEMS   12607488

// ---------------- scratch (device globals; no allocation allowed) ----------------
__device__ float g_pooled[NB * CINC * 50];              // 50 pooled positions per (b,c)
__device__ float g_ybr[NB * 128 * 50];                  // branch activations
__device__ float g_Z[NB * CINC * 50];                   // w_conv-projected branches
__device__ float g_xmid[(size_t)NB * CINC * SP];        // after 1x1 conv + BN + relu
__device__ float g_seg[NB * NC * SP];                   // after 3x3 conv (60x60)
__device__ float g_feamap[NB * NC * SP];                // pooled one-hot argmax

__device__ __forceinline__ int branch_of(int j) {
    return (j == 0) ? 0 : (j < 5 ? 1 : (j < 14 ? 2 : 3));
}

// ======================= K1: all 4 adaptive avg pools in one pass =======================
// p=6 -> 36 sums of 10x10 blocks; p=3 (20x20) = 2x2 of those; p=2 (30x30) = 3x3; p=1 = all.
__global__ void k_pool(const float* __restrict__ feat) {
    int bc = blockIdx.x;                     // b*512 + c
    const float* src = feat + (size_t)bc * SP;
    __shared__ float s6[36];
    int t = threadIdx.x;
    if (t < 36) s6[t] = 0.f;
    __syncthreads();
    for (int i = t; i < SP; i += 128) {
        int h = i / 60, w = i % 60;
        atomicAdd(&s6[(h / 10) * 6 + (w / 10)], src[i]);
    }
    __syncthreads();
    float* P = g_pooled + (size_t)bc * 50;
    if (t < 36) P[14 + t] = s6[t] * (1.f / 100.f);                       // p=6
    if (t < 9) {                                                          // p=3
        int r = t / 3, c = t % 3;
        float s = s6[(2*r)*6 + 2*c] + s6[(2*r)*6 + 2*c+1]
                + s6[(2*r+1)*6 + 2*c] + s6[(2*r+1)*6 + 2*c+1];
        P[5 + t] = s * (1.f / 400.f);
    }
    if (t < 4) {                                                          // p=2
        int r = t / 2, c = t % 2;
        float s = 0.f;
        for (int rr = 0; rr < 3; rr++)
            for (int cc = 0; cc < 3; cc++) s += s6[(3*r+rr)*6 + 3*c+cc];
        P[1 + t] = s * (1.f / 900.f);
    }
    if (t == 0) {                                                         // p=1
        float s = 0.f;
        for (int i = 0; i < 36; i++) s += s6[i];
        P[0] = s * (1.f / 3600.f);
    }
}

// ======================= K2: branch 1x1 convs + bias/BN + relu =======================
__global__ void k_branch(const float* __restrict__ wpsp, const float* __restrict__ bpsp0,
                         const float* __restrict__ bg, const float* __restrict__ bb,
                         const float* __restrict__ bm, const float* __restrict__ bv) {
    int b = blockIdx.x, j = blockIdx.y;
    int i = branch_of(j);
    __shared__ float sp[512];
    for (int c = threadIdx.x; c < 512; c += 128)
        sp[c] = g_pooled[((size_t)b * 512 + c) * 50 + j];
    __syncthreads();
    int oc = threadIdx.x;                    // 128 threads
    const float* wr = wpsp + ((size_t)i * 128 + oc) * 512;
    float acc = 0.f;
    #pragma unroll 8
    for (int c = 0; c < 512; c++) acc = fmaf(wr[c], sp[c], acc);
    if (i == 0) {
        acc += bpsp0[oc];
    } else {
        int r = i - 1;
        float sc = bg[r*128 + oc] * rsqrtf(bv[r*128 + oc] + 1e-5f);
        acc = fmaf(acc - bm[r*128 + oc], sc, bb[r*128 + oc]);
    }
    g_ybr[((size_t)b * 128 + oc) * 50 + j] = fmaxf(acc, 0.f);
}

// ======================= K3: Z = Wconv[:, branch cols] @ y  (low-rank trick) ==========
__global__ void k_Z(const float* __restrict__ wconv) {
    int b = blockIdx.x, j = blockIdx.y;
    int i = branch_of(j);
    __shared__ float sy[128];
    if (threadIdx.x < 128) sy[threadIdx.x] = g_ybr[((size_t)b * 128 + threadIdx.x) * 50 + j];
    __syncthreads();
    for (int oc = threadIdx.x; oc < 512; oc += blockDim.x) {
        const float* wr = wconv + (size_t)oc * 1024 + i * 128;
        float acc = 0.f;
        #pragma unroll 8
        for (int c = 0; c < 128; c++) acc = fmaf(wr[c], sy[c], acc);
        g_Z[((size_t)b * 512 + oc) * 50 + j] = acc;
    }
}

// ======================= K4: main 512x512 GEMM over 3600 pixels per batch ============
// xmid = relu(bn( Wfeat @ feat + interp(Z) ))
struct IW { int i0, i1, i2, i3; float w00, w01, w10, w11; };

__device__ __forceinline__ IW make_iw(int h, int w, int p, int base) {
    float ratio = (float)(p - 1) / 59.0f;
    float ry = (float)h * ratio;
    float rx = (float)w * ratio;
    int y0 = (int)floorf(ry), x0 = (int)floorf(rx);
    int y1 = min(y0 + 1, p - 1), x1 = min(x0 + 1, p - 1);
    float fy = ry - (float)y0, fx = rx - (float)x0;
    IW r;
    r.i0 = base + y0 * p + x0; r.i1 = base + y0 * p + x1;
    r.i2 = base + y1 * p + x0; r.i3 = base + y1 * p + x1;
    r.w00 = (1.f - fy) * (1.f - fx); r.w01 = (1.f - fy) * fx;
    r.w10 = fy * (1.f - fx);         r.w11 = fy * fx;
    return r;
}

#define BM 64
#define BN 64
#define BK 16
__global__ void k_gemm(const float* __restrict__ wconv, const float* __restrict__ feat,
                       const float* __restrict__ bg, const float* __restrict__ bb,
                       const float* __restrict__ bm, const float* __restrict__ bv) {
    int nt = blockIdx.x, mt = blockIdx.y, b = blockIdx.z;
    __shared__ float As[BK][BM];
    __shared__ float Bs[BK][BN];
    int tid = threadIdx.x;
    int tx = tid & 15, ty = tid >> 4;
    float acc[4][4];
    #pragma unroll
    for (int i = 0; i < 4; i++)
        #pragma unroll
        for (int j = 0; j < 4; j++) acc[i][j] = 0.f;

    const float* Bbase = feat + (size_t)b * CINC * SP;
    for (int kk = 0; kk < 512; kk += BK) {
        #pragma unroll
        for (int l = tid; l < BM * BK; l += 256) {
            int m = l >> 4, k = l & 15;
            As[k][m] = wconv[((size_t)(mt * 64 + m)) * 1024 + 512 + kk + k];
        }
        #pragma unroll
        for (int l = tid; l < BK * BN; l += 256) {
            int k = l >> 6, n = l & 63;
            int s = nt * 64 + n;
            Bs[k][n] = (s < SP) ? Bbase[(size_t)(kk + k) * SP + s] : 0.f;
        }
        __syncthreads();
        #pragma unroll
        for (int k = 0; k < BK; k++) {
            float a[4], bv4[4];
            #pragma unroll
            for (int i = 0; i < 4; i++) a[i] = As[k][ty * 4 + i];
            #pragma unroll
            for (int i = 0; i < 4; i++) bv4[i] = Bs[k][tx * 4 + i];
            #pragma unroll
            for (int i = 0; i < 4; i++)
                #pragma unroll
                for (int j = 0; j < 4; j++)
                    acc[i][j] = fmaf(a[i], bv4[j], acc[i][j]);
        }
        __syncthreads();
    }

    // epilogue: + bilinear(Z) for the 4 pool branches, BN, relu
    #pragma unroll
    for (int j = 0; j < 4; j++) {
        int s = nt * 64 + tx * 4 + j;
        if (s >= SP) continue;
        int h = s / 60, w = s % 60;
        IW w2 = make_iw(h, w, 2, 1);
        IW w3 = make_iw(h, w, 3, 5);
        IW w6 = make_iw(h, w, 6, 14);
        #pragma unroll
        for (int i = 0; i < 4; i++) {
            int oc = mt * 64 + ty * 4 + i;
            const float* Zr = g_Z + ((size_t)b * 512 + oc) * 50;
            float val = acc[i][j] + Zr[0];
            val += w2.w00 * Zr[w2.i0] + w2.w01 * Zr[w2.i1] + w2.w10 * Zr[w2.i2] + w2.w11 * Zr[w2.i3];
            val += w3.w00 * Zr[w3.i0] + w3.w01 * Zr[w3.i1] + w3.w10 * Zr[w3.i2] + w3.w11 * Zr[w3.i3];
            val += w6.w00 * Zr[w6.i0] + w6.w01 * Zr[w6.i1] + w6.w10 * Zr[w6.i2] + w6.w11 * Zr[w6.i3];
            float sc = bg[oc] * rsqrtf(bv[oc] + 1e-5f);
            val = fmaf(val - bm[oc], sc, bb[oc]);
            g_xmid[((size_t)b * 512 + oc) * SP + s] = fmaxf(val, 0.f);
        }
    }
}

// ======================= K5: 3x3 conv 512 -> 19 (+bias), SAME padding ==================
__global__ void k_conv3(const float* __restrict__ wseg, const float* __restrict__ bseg) {
    int h = blockIdx.x, b = blockIdx.y;
    int t = threadIdx.x;                       // 64 threads, lane = output column
    __shared__ float sh[16][3][64];            // [chan][row-1..+1][w+1], borders zeroed
    __shared__ __align__(16) float shw[16][9][20]; // weights, 19 padded to 20 for float4
    float4 acc[5];
    #pragma unroll
    for (int i = 0; i < 5; i++) acc[i] = make_float4(0.f, 0.f, 0.f, 0.f);

    const float* xb = g_xmid + (size_t)b * CINC * SP;
    for (int cc = 0; cc < 512; cc += 16) {
        for (int l = t; l < 16 * 3 * 62; l += 64) {
            int c = l / 186, rem = l % 186;
            int r = rem / 62, wp = rem % 62;
            int hh = h + r - 1, ww = wp - 1;
            float v = 0.f;
            if (hh >= 0 && hh < 60 && ww >= 0 && ww < 60)
                v = xb[(size_t)(cc + c) * SP + hh * 60 + ww];
            sh[c][r][wp] = v;
        }
        for (int l = t; l < 16 * 9 * 20; l += 64) {
            int c = l / 180, rem = l % 180;
            int tap = rem / 20, o = rem % 20;
            shw[c][tap][o] = (o < 19) ? wseg[((size_t)o * 512 + cc + c) * 9 + tap] : 0.f;
        }
        __syncthreads();
        if (t < 60) {
            #pragma unroll 4
            for (int c = 0; c < 16; c++) {
                #pragma unroll
                for (int ky = 0; ky < 3; ky++) {
                    #pragma unroll
                    for (int kx = 0; kx < 3; kx++) {
                        float v = sh[c][ky][t + kx];
                        const float4* wp4 = reinterpret_cast<const float4*>(&shw[c][ky * 3 + kx][0]);
                        #pragma unroll
                        for (int g2 = 0; g2 < 5; g2++) {
                            float4 wv = wp4[g2];
                            acc[g2].x = fmaf(v, wv.x, acc[g2].x);
                            acc[g2].y = fmaf(v, wv.y, acc[g2].y);
                            acc[g2].z = fmaf(v, wv.z, acc[g2].z);
                            acc[g2].w = fmaf(v, wv.w, acc[g2].w);
                        }
                    }
                }
            }
        }
        __syncthreads();
    }
    if (t < 60) {
        float* sb = g_seg + (size_t)b * NC * SP + h * 60 + t;
        #pragma unroll
        for (int g2 = 0; g2 < 5; g2++) {
            int o = g2 * 4;
            sb[(size_t)o * SP] = acc[g2].x + bseg[o];
            if (o + 1 < 19) sb[(size_t)(o + 1) * SP] = acc[g2].y + bseg[o + 1];
            if (o + 2 < 19) sb[(size_t)(o + 2) * SP] = acc[g2].z + bseg[o + 2];
            if (o + 3 < 19) sb[(size_t)(o + 3) * SP] = acc[g2].w + bseg[o + 3];
        }
    }
}

// ====== K6: bilinear 60->480 (align_corners) + argmax + 8x8 one-hot pooling ============
__global__ void k_up(float* __restrict__ out) {
    int wf = blockIdx.x, hf = blockIdx.y, b = blockIdx.z;
    int t = threadIdx.x;                         // 64 = one 8x8 block of pixels
    int py = t >> 3, px = t & 7;
    int H = hf * 8 + py, W = wf * 8 + px;
    float ry = (float)H * (59.0f / 479.0f);
    float rx = (float)W * (59.0f / 479.0f);
    int y0 = (int)floorf(ry), x0 = (int)floorf(rx);
    int y1 = min(y0 + 1, 59), x1 = min(x0 + 1, 59);
    float fy = ry - (float)y0, fx = rx - (float)x0;
    const float* sp = g_seg + (size_t)b * NC * SP;
    float best = -3.4e38f; int bidx = 0;
    #pragma unroll 1
    for (int c = 0; c < NC; c++) {
        const float* p = sp + (size_t)c * SP;
        float v00 = p[y0 * 60 + x0], v01 = p[y0 * 60 + x1];
        float v10 = p[y1 * 60 + x0], v11 = p[y1 * 60 + x1];
        float top = (1.f - fx) * v00 + fx * v01;
        float bot = (1.f - fx) * v10 + fx * v11;
        float v = (1.f - fy) * top + fy * bot;
        out[(((size_t)(b * NC + c)) * HIR + H) * HIR + W] = v;
        if (v > best) { best = v; bidx = c; }
    }
    __shared__ int cnt[NC];
    if (t < NC) cnt[t] = 0;
    __syncthreads();
    atomicAdd(&cnt[bidx], 1);
    __syncthreads();
    if (t < NC)
        g_feamap[((size_t)(b * NC + t)) * SP + hf * 60 + wf] = (float)cnt[t] * (1.f / 64.f);
}

// ====== K7: unfold + attention matmul + fold + x = x*(1+corr), in-place on d_out =======
__global__ void k_corr(const float* __restrict__ att, float* __restrict__ out) {
    int bc = blockIdx.x;                        // b*19 + c
    int chunk = blockIdx.y;                     // 18 chunks of 128 image patches
    __shared__ float sf[SP];                    // feamap tile for this (b,c)
    __shared__ float sa[4][36];
    for (int l = threadIdx.x; l < SP; l += 128) sf[l] = g_feamap[(size_t)bc * SP + l];
    __syncthreads();
    int warp = threadIdx.x >> 5, lane = threadIdx.x & 31;
    int q0 = lane, q1 = lane + 32, q2 = lane + 64, q3 = lane + 96;
    bool has3 = (q3 < 100);
    int o0 = (q0 / 10) * 60 + q0 % 10;
    int o1 = (q1 / 10) * 60 + q1 % 10;
    int o2 = (q2 / 10) * 60 + q2 % 10;
    int o3 = has3 ? (q3 / 10) * 60 + q3 % 10 : 0;

    for (int tt = 0; tt < 32; tt++) {
        int bi = chunk * 128 + warp * 32 + tt;
        const float* ar = att + ((size_t)bc * 2304 + bi) * 36;
        float v = ar[lane];
        float v2 = 0.f;
        int nz = (v != 0.f) ? 1 : 0;
        if (lane < 4) { v2 = ar[32 + lane]; nz += (v2 != 0.f) ? 1 : 0; }
        #pragma unroll
        for (int s = 16; s; s >>= 1) nz += __shfl_xor_sync(0xffffffffu, nz, s);
        float scale = 1.f / ((float)nz + 1e-5f);
        sa[warp][lane] = v * scale;
        if (lane < 4) sa[warp][32 + lane] = v2 * scale;
        __syncwarp();
        float c0 = 0.f, c1 = 0.f, c2 = 0.f, c3 = 0.f;
        #pragma unroll
        for (int k = 0; k < 36; k++) {
            int bk = (k / 6) * 600 + (k % 6) * 10;
            float a = sa[warp][k];
            c0 = fmaf(a, sf[bk + o0], c0);
            c1 = fmaf(a, sf[bk + o1], c1);
            c2 = fmaf(a, sf[bk + o2], c2);
            c3 = fmaf(a, sf[bk + o3], c3);
        }
        int R = bi / 48, Cc = bi % 48;
        size_t base = (size_t)bc * HIR * HIR + (size_t)(R * 10) * HIR + Cc * 10;
        size_t i0 = base + (size_t)(q0 / 10) * HIR + q0 % 10;
        float x = out[i0]; out[i0] = fmaf(c0, x, x);
        size_t i1 = base + (size_t)(q1 / 10) * HIR + q1 % 10;
        x = out[i1]; out[i1] = fmaf(c1, x, x);
        size_t i2 = base + (size_t)(q2 / 10) * HIR + q2 % 10;
        x = out[i2]; out[i2] = fmaf(c2, x, x);
        if (has3) {
            size_t i3 = base + (size_t)(q3 / 10) * HIR + q3 % 10;
            x = out[i3]; out[i3] = fmaf(c3, x, x);
        }
        __syncwarp();
    }
}

// ======================= launch =======================
extern "C" void kernel_launch(void* const* d_in, const int* in_sizes, int n_in,
                              void* d_out, int out_size) {
    const float* feat   = (const float*)d_in[0];
    const float* attn   = (const float*)d_in[1];
    const float* w_psp  = (const float*)d_in[2];
    const float* b_psp0 = (const float*)d_in[3];
    const float* bpg    = (const float*)d_in[4];
    const float* bpb    = (const float*)d_in[5];
    const float* bpm    = (const float*)d_in[6];
    const float* bpv    = (const float*)d_in[7];
    const float* w_conv = (const float*)d_in[8];
    const float* bcg    = (const float*)d_in[9];
    const float* bcb    = (const float*)d_in[10];
    const float* bcm    = (const float*)d_in[11];
    const float* bcv    = (const float*)d_in[12];
    const float* wseg   = (const float*)d_in[13];
    const float* bseg   = (const float*)d_in[14];
    float* out = (float*)d_out;

    k_pool<<<NB * CINC, 128>>>(feat);
    k_branch<<<dim3(NB, 50), 128>>>(w_psp, b_psp0, bpg, bpb, bpm, bpv);
    k_Z<<<dim3(NB, 50), 256>>>(w_conv);
    k_gemm<<<dim3(57, 8, NB), 256>>>(w_conv, feat, bcg, bcb, bcm, bcv);
    k_conv3<<<dim3(60, NB), 64>>>(wseg, bseg);
    k_up<<<dim3(60, 60, NB), 64>>>(out);
    k_corr<<<dim3(NB * NC, 18), 128>>>(attn, out);
    if (out_size >= XOUT_ELEMS + ATT_ELEMS) {
        cudaMemcpyAsync(out + XOUT_ELEMS, attn, (size_t)ATT_ELEMS * sizeof(float),
                        cudaMemcpyDeviceToDevice);
    }
}

// round 4
// speedup vs baseline: 1.6282x; 1.6282x over previous
#include <cuda_runtime.h>
#include <math.h>
#include <stdint.h>

// ---------------- problem constants ----------------
#define NB   8
#define CINC 512
#define SP   3600            // 60*60
#define NC   19
#define HIR  480

#define XOUT_ELEMS  35020800
#define ATT_ELEMS   12607488

// ---------------- scratch (device globals) ----------------
__device__ float g_pooled[NB * CINC * 50];
__device__ float g_ybr[NB * 128 * 50];
__device__ float g_Z[NB * CINC * 50];
__device__ float g_xmid[(size_t)NB * CINC * SP];
__device__ float g_seg[NB * NC * SP];
__device__ float g_seg4[4 * NB * NC * SP];   // conv3 channel-chunk partials
__device__ float g_feamap[NB * NC * SP];

__device__ __forceinline__ int branch_of(int j) {
    return (j == 0) ? 0 : (j < 5 ? 1 : (j < 14 ? 2 : 3));
}

// ======================= K1: all 4 adaptive avg pools, no atomics =======================
__global__ void k_pool(const float* __restrict__ feat) {
    int bc = blockIdx.x;                     // b*512 + c
    const float* src = feat + (size_t)bc * SP;
    __shared__ float seg[360];               // 60 rows x 6 col-segments of 10
    __shared__ float s6[36];
    int t = threadIdx.x;                     // 128
    for (int i = t; i < 360; i += 128) {
        int row = i / 6, cs = i % 6;
        const float* p = src + row * 60 + cs * 10;
        float s = 0.f;
        #pragma unroll
        for (int j = 0; j < 10; j++) s += p[j];
        seg[i] = s;
    }
    __syncthreads();
    if (t < 36) {
        int r = t / 6, c = t % 6;
        float s = 0.f;
        #pragma unroll
        for (int rr = 0; rr < 10; rr++) s += seg[(r * 10 + rr) * 6 + c];
        s6[t] = s;
    }
    __syncthreads();
    float* P = g_pooled + (size_t)bc * 50;
    if (t < 36) P[14 + t] = s6[t] * (1.f / 100.f);
    if (t < 9) {
        int r = t / 3, c = t % 3;
        float s = s6[(2*r)*6 + 2*c] + s6[(2*r)*6 + 2*c+1]
                + s6[(2*r+1)*6 + 2*c] + s6[(2*r+1)*6 + 2*c+1];
        P[5 + t] = s * (1.f / 400.f);
    }
    if (t < 4) {
        int r = t / 2, c = t % 2;
        float s = 0.f;
        for (int rr = 0; rr < 3; rr++)
            for (int cc = 0; cc < 3; cc++) s += s6[(3*r+rr)*6 + 3*c+cc];
        P[1 + t] = s * (1.f / 900.f);
    }
    if (t == 0) {
        float s = 0.f;
        for (int i = 0; i < 36; i++) s += s6[i];
        P[0] = s * (1.f / 3600.f);
    }
}

// ======================= K2: branch 1x1 convs + bias/BN + relu =======================
__global__ void k_branch(const float* __restrict__ wpsp, const float* __restrict__ bpsp0,
                         const float* __restrict__ bg, const float* __restrict__ bb,
                         const float* __restrict__ bm, const float* __restrict__ bv) {
    int b = blockIdx.x, j = blockIdx.y;
    int i = branch_of(j);
    __shared__ float sp[512];
    for (int c = threadIdx.x; c < 512; c += 128)
        sp[c] = g_pooled[((size_t)b * 512 + c) * 50 + j];
    __syncthreads();
    int oc = threadIdx.x;
    const float* wr = wpsp + ((size_t)i * 128 + oc) * 512;
    float acc = 0.f;
    #pragma unroll 8
    for (int c = 0; c < 512; c++) acc = fmaf(wr[c], sp[c], acc);
    if (i == 0) {
        acc += bpsp0[oc];
    } else {
        int r = i - 1;
        float sc = bg[r*128 + oc] * rsqrtf(bv[r*128 + oc] + 1e-5f);
        acc = fmaf(acc - bm[r*128 + oc], sc, bb[r*128 + oc]);
    }
    g_ybr[((size_t)b * 128 + oc) * 50 + j] = fmaxf(acc, 0.f);
}

// ======================= K3: Z = Wconv[:, branch cols] @ y =======================
__global__ void k_Z(const float* __restrict__ wconv) {
    int b = blockIdx.x, j = blockIdx.y;
    int i = branch_of(j);
    __shared__ float sy[128];
    if (threadIdx.x < 128) sy[threadIdx.x] = g_ybr[((size_t)b * 128 + threadIdx.x) * 50 + j];
    __syncthreads();
    for (int oc = threadIdx.x; oc < 512; oc += blockDim.x) {
        const float* wr = wconv + (size_t)oc * 1024 + i * 128;
        float acc = 0.f;
        #pragma unroll 8
        for (int c = 0; c < 128; c++) acc = fmaf(wr[c], sy[c], acc);
        g_Z[((size_t)b * 512 + oc) * 50 + j] = acc;
    }
}

// ======================= K4: tf32 tensor-core GEMM 512x512 @ 3600 px/batch ============
struct IW { int i0, i1, i2, i3; float w00, w01, w10, w11; };

__device__ __forceinline__ IW make_iw(int h, int w, int p, int base) {
    float ratio = (float)(p - 1) / 59.0f;
    float ry = (float)h * ratio;
    float rx = (float)w * ratio;
    int y0 = (int)floorf(ry), x0 = (int)floorf(rx);
    int y1 = min(y0 + 1, p - 1), x1 = min(x0 + 1, p - 1);
    float fy = ry - (float)y0, fx = rx - (float)x0;
    IW r;
    r.i0 = base + y0 * p + x0; r.i1 = base + y0 * p + x1;
    r.i2 = base + y1 * p + x0; r.i3 = base + y1 * p + x1;
    r.w00 = (1.f - fy) * (1.f - fx); r.w01 = (1.f - fy) * fx;
    r.w10 = fy * (1.f - fx);         r.w11 = fy * fx;
    return r;
}

__device__ __forceinline__ uint32_t f2tf32(float x) {
    uint32_t r;
    asm("cvt.rna.tf32.f32 %0, %1;" : "=r"(r) : "f"(x));
    return r;
}

// BM=128, BN=64, BK=32. sA: [128][36] floats (pad 32->36), sB: [32][72] (pad 64->72).
#define SA_STRIDE 36
#define SB_STRIDE 72
__global__ void __launch_bounds__(256, 2)
k_gemm(const float* __restrict__ wconv, const float* __restrict__ feat,
       const float* __restrict__ bg, const float* __restrict__ bb,
       const float* __restrict__ bm, const float* __restrict__ bv) {
    int nt = blockIdx.x, mt = blockIdx.y, b = blockIdx.z;
    __shared__ float smem_f[128 * SA_STRIDE + 32 * SB_STRIDE];   // 4608 + 2304 floats
    uint32_t* sAu = (uint32_t*)smem_f;                 // [128][36]
    uint32_t* sBu = (uint32_t*)(smem_f + 128 * SA_STRIDE);  // [32][72]

    int tid = threadIdx.x;
    int lane = tid & 31, wid = tid >> 5;
    int gid = lane >> 2, tid4 = lane & 3;
    int warp_m = wid >> 2, warp_n = wid & 3;       // 2 x 4
    int m_base = warp_m * 64, n_base = warp_n * 16;

    float acc[4][2][4];
    #pragma unroll
    for (int mi = 0; mi < 4; mi++)
        #pragma unroll
        for (int ni = 0; ni < 2; ni++)
            #pragma unroll
            for (int r = 0; r < 4; r++) acc[mi][ni][r] = 0.f;

    const float* Bbase = feat + (size_t)b * CINC * SP;

    for (int kk = 0; kk < 512; kk += 32) {
        // ---- fill A: wconv rows mt*128..+128, cols 512+kk..+32 -> sA[m][k] ----
        #pragma unroll
        for (int r = 0; r < 4; r++) {
            int idx = r * 256 + tid;
            int m = idx >> 3, k4 = idx & 7;
            const float4 v = *(const float4*)&wconv[((size_t)(mt * 128 + m)) * 1024 + 512 + kk + k4 * 4];
            uint32_t* d = &sAu[m * SA_STRIDE + k4 * 4];
            d[0] = f2tf32(v.x); d[1] = f2tf32(v.y); d[2] = f2tf32(v.z); d[3] = f2tf32(v.w);
        }
        // ---- fill B: feat rows kk..kk+32, cols nt*64..+64 -> sB[k][n] ----
        #pragma unroll
        for (int r = 0; r < 2; r++) {
            int idx = r * 256 + tid;
            int k = idx >> 4, n4 = idx & 15;
            int s0 = nt * 64 + n4 * 4;
            float4 v = make_float4(0.f, 0.f, 0.f, 0.f);
            if (s0 < SP)  // SP%4==0 so whole float4 is in range
                v = *(const float4*)&Bbase[(size_t)(kk + k) * SP + s0];
            uint32_t* d = &sBu[k * SB_STRIDE + n4 * 4];
            d[0] = f2tf32(v.x); d[1] = f2tf32(v.y); d[2] = f2tf32(v.z); d[3] = f2tf32(v.w);
        }
        __syncthreads();

        #pragma unroll
        for (int k0 = 0; k0 < 32; k0 += 8) {
            uint32_t af[4][4], bf[2][2];
            #pragma unroll
            for (int mi = 0; mi < 4; mi++) {
                int r0 = (m_base + mi * 16 + gid) * SA_STRIDE;
                af[mi][0] = sAu[r0 + k0 + tid4];
                af[mi][1] = sAu[r0 + 8 * SA_STRIDE + k0 + tid4];
                af[mi][2] = sAu[r0 + k0 + tid4 + 4];
                af[mi][3] = sAu[r0 + 8 * SA_STRIDE + k0 + tid4 + 4];
            }
            #pragma unroll
            for (int ni = 0; ni < 2; ni++) {
                int c = n_base + ni * 8 + gid;
                bf[ni][0] = sBu[(k0 + tid4) * SB_STRIDE + c];
                bf[ni][1] = sBu[(k0 + tid4 + 4) * SB_STRIDE + c];
            }
            #pragma unroll
            for (int mi = 0; mi < 4; mi++)
                #pragma unroll
                for (int ni = 0; ni < 2; ni++)
                    asm volatile(
                        "mma.sync.aligned.m16n8k8.row.col.f32.tf32.tf32.f32 "
                        "{%0,%1,%2,%3}, {%4,%5,%6,%7}, {%8,%9}, {%0,%1,%2,%3};"
                        : "+f"(acc[mi][ni][0]), "+f"(acc[mi][ni][1]),
                          "+f"(acc[mi][ni][2]), "+f"(acc[mi][ni][3])
                        : "r"(af[mi][0]), "r"(af[mi][1]), "r"(af[mi][2]), "r"(af[mi][3]),
                          "r"(bf[ni][0]), "r"(bf[ni][1]));
        }
        __syncthreads();
    }

    // ---- stage Z slice [128][50] into reused smem (pad to 52) ----
    float* sZ = smem_f;
    for (int idx = tid; idx < 128 * 50; idx += 256) {
        int row = idx / 50, j = idx % 50;
        sZ[row * 52 + j] = g_Z[((size_t)b * 512 + mt * 128 + row) * 50 + j];
    }
    __syncthreads();

    // BN constants per (mi, half)
    float scv[8], mbv8[8], btv[8];
    #pragma unroll
    for (int mi = 0; mi < 4; mi++)
        #pragma unroll
        for (int hf2 = 0; hf2 < 2; hf2++) {
            int oc = mt * 128 + m_base + mi * 16 + gid + hf2 * 8;
            int e = mi * 2 + hf2;
            scv[e] = bg[oc] * rsqrtf(bv[oc] + 1e-5f);
            mbv8[e] = bm[oc]; btv[e] = bb[oc];
        }

    #pragma unroll
    for (int u = 0; u < 4; u++) {
        int ni = u >> 1, j = u & 1;
        int s = nt * 64 + n_base + ni * 8 + tid4 * 2 + j;
        if (s >= SP) continue;
        int h = s / 60, w = s % 60;
        IW w2 = make_iw(h, w, 2, 1);
        IW w3 = make_iw(h, w, 3, 5);
        IW w6 = make_iw(h, w, 6, 14);
        #pragma unroll
        for (int mi = 0; mi < 4; mi++)
            #pragma unroll
            for (int hf2 = 0; hf2 < 2; hf2++) {
                int row = m_base + mi * 16 + gid + hf2 * 8;
                int oc = mt * 128 + row;
                const float* zr = &sZ[row * 52];
                float val = acc[mi][ni][hf2 * 2 + j] + zr[0];
                val += w2.w00 * zr[w2.i0] + w2.w01 * zr[w2.i1] + w2.w10 * zr[w2.i2] + w2.w11 * zr[w2.i3];
                val += w3.w00 * zr[w3.i0] + w3.w01 * zr[w3.i1] + w3.w10 * zr[w3.i2] + w3.w11 * zr[w3.i3];
                val += w6.w00 * zr[w6.i0] + w6.w01 * zr[w6.i1] + w6.w10 * zr[w6.i2] + w6.w11 * zr[w6.i3];
                int e = mi * 2 + hf2;
                val = fmaf(val - mbv8[e], scv[e], btv[e]);
                g_xmid[((size_t)b * 512 + oc) * SP + s] = fmaxf(val, 0.f);
            }
    }
}

// ======================= K5: 3x3 conv, channel-split x4, partials ==================
__global__ void k_conv3(const float* __restrict__ wseg) {
    int h = blockIdx.x, q = blockIdx.y, b = blockIdx.z;
    int t = threadIdx.x;                       // 64 threads
    __shared__ float sh[16][3][64];
    __shared__ __align__(16) float shw[16][9][20];
    float4 acc[5];
    #pragma unroll
    for (int i = 0; i < 5; i++) acc[i] = make_float4(0.f, 0.f, 0.f, 0.f);

    const float* xb = g_xmid + (size_t)b * CINC * SP;
    for (int cc = q * 128; cc < q * 128 + 128; cc += 16) {
        for (int l = t; l < 16 * 3 * 62; l += 64) {
            int c = l / 186, rem = l % 186;
            int r = rem / 62, wp = rem % 62;
            int hh = h + r - 1, ww = wp - 1;
            float v = 0.f;
            if (hh >= 0 && hh < 60 && ww >= 0 && ww < 60)
                v = xb[(size_t)(cc + c) * SP + hh * 60 + ww];
            sh[c][r][wp] = v;
        }
        for (int l = t; l < 16 * 9 * 20; l += 64) {
            int c = l / 180, rem = l % 180;
            int tap = rem / 20, o = rem % 20;
            shw[c][tap][o] = (o < 19) ? wseg[((size_t)o * 512 + cc + c) * 9 + tap] : 0.f;
        }
        __syncthreads();
        if (t < 60) {
            #pragma unroll 4
            for (int c = 0; c < 16; c++) {
                #pragma unroll
                for (int ky = 0; ky < 3; ky++) {
                    #pragma unroll
                    for (int kx = 0; kx < 3; kx++) {
                        float v = sh[c][ky][t + kx];
                        const float4* wp4 = reinterpret_cast<const float4*>(&shw[c][ky * 3 + kx][0]);
                        #pragma unroll
                        for (int g2 = 0; g2 < 5; g2++) {
                            float4 wv = wp4[g2];
                            acc[g2].x = fmaf(v, wv.x, acc[g2].x);
                            acc[g2].y = fmaf(v, wv.y, acc[g2].y);
                            acc[g2].z = fmaf(v, wv.z, acc[g2].z);
                            acc[g2].w = fmaf(v, wv.w, acc[g2].w);
                        }
                    }
                }
            }
        }
        __syncthreads();
    }
    if (t < 60) {
        float* sb = g_seg4 + (size_t)(q * NB + b) * NC * SP + h * 60 + t;
        #pragma unroll
        for (int g2 = 0; g2 < 5; g2++) {
            int o = g2 * 4;
            sb[(size_t)o * SP] = acc[g2].x;
            if (o + 1 < 19) sb[(size_t)(o + 1) * SP] = acc[g2].y;
            if (o + 2 < 19) sb[(size_t)(o + 2) * SP] = acc[g2].z;
            if (o + 3 < 19) sb[(size_t)(o + 3) * SP] = acc[g2].w;
        }
    }
}

// deterministic reduce of the 4 channel-chunk partials + bias
__global__ void k_segreduce(const float* __restrict__ bseg) {
    int e = blockIdx.x * 256 + threadIdx.x;
    const int TOT = NB * NC * SP;
    if (e >= TOT) return;
    int o = (e / SP) % NC;
    float s = bseg[o];
    #pragma unroll
    for (int q = 0; q < 4; q++) s += g_seg4[(size_t)q * TOT + e];
    g_seg[e] = s;
}

// ====== K6: bilinear 60->480 + argmax + 8x8 one-hot pooling ============
__global__ void k_up(float* __restrict__ out) {
    int wf = blockIdx.x, hf = blockIdx.y, b = blockIdx.z;
    int t = threadIdx.x;
    int py = t >> 3, px = t & 7;
    int H = hf * 8 + py, W = wf * 8 + px;
    float ry = (float)H * (59.0f / 479.0f);
    float rx = (float)W * (59.0f / 479.0f);
    int y0 = (int)floorf(ry), x0 = (int)floorf(rx);
    int y1 = min(y0 + 1, 59), x1 = min(x0 + 1, 59);
    float fy = ry - (float)y0, fx = rx - (float)x0;
    const float* sp = g_seg + (size_t)b * NC * SP;
    float best = -3.4e38f; int bidx = 0;
    #pragma unroll 1
    for (int c = 0; c < NC; c++) {
        const float* p = sp + (size_t)c * SP;
        float v00 = p[y0 * 60 + x0], v01 = p[y0 * 60 + x1];
        float v10 = p[y1 * 60 + x0], v11 = p[y1 * 60 + x1];
        float top = (1.f - fx) * v00 + fx * v01;
        float bot = (1.f - fx) * v10 + fx * v11;
        float v = (1.f - fy) * top + fy * bot;
        out[(((size_t)(b * NC + c)) * HIR + H) * HIR + W] = v;
        if (v > best) { best = v; bidx = c; }
    }
    __shared__ int cnt[NC];
    if (t < NC) cnt[t] = 0;
    __syncthreads();
    atomicAdd(&cnt[bidx], 1);
    __syncthreads();
    if (t < NC)
        g_feamap[((size_t)(b * NC + t)) * SP + hf * 60 + wf] = (float)cnt[t] * (1.f / 64.f);
}

// ====== K7: unfold + attention matmul + fold + x = x*(1+corr) ============
__global__ void k_corr(const float* __restrict__ att, float* __restrict__ out) {
    int bc = blockIdx.x;
    int chunk = blockIdx.y;
    __shared__ float sf[SP];
    __shared__ float sa[4][36];
    for (int l = threadIdx.x; l < SP; l += 128) sf[l] = g_feamap[(size_t)bc * SP + l];
    __syncthreads();
    int warp = threadIdx.x >> 5, lane = threadIdx.x & 31;
    int q0 = lane, q1 = lane + 32, q2 = lane + 64, q3 = lane + 96;
    bool has3 = (q3 < 100);
    int o0 = (q0 / 10) * 60 + q0 % 10;
    int o1 = (q1 / 10) * 60 + q1 % 10;
    int o2 = (q2 / 10) * 60 + q2 % 10;
    int o3 = has3 ? (q3 / 10) * 60 + q3 % 10 : 0;

    for (int tt = 0; tt < 32; tt++) {
        int bi = chunk * 128 + warp * 32 + tt;
        const float* ar = att + ((size_t)bc * 2304 + bi) * 36;
        float v = ar[lane];
        float v2 = 0.f;
        int nz = (v != 0.f) ? 1 : 0;
        if (lane < 4) { v2 = ar[32 + lane]; nz += (v2 != 0.f) ? 1 : 0; }
        #pragma unroll
        for (int s = 16; s; s >>= 1) nz += __shfl_xor_sync(0xffffffffu, nz, s);
        float scale = 1.f / ((float)nz + 1e-5f);
        sa[warp][lane] = v * scale;
        if (lane < 4) sa[warp][32 + lane] = v2 * scale;
        __syncwarp();
        float c0 = 0.f, c1 = 0.f, c2 = 0.f, c3 = 0.f;
        #pragma unroll
        for (int k = 0; k < 36; k++) {
            int bk = (k / 6) * 600 + (k % 6) * 10;
            float a = sa[warp][k];
            c0 = fmaf(a, sf[bk + o0], c0);
            c1 = fmaf(a, sf[bk + o1], c1);
            c2 = fmaf(a, sf[bk + o2], c2);
            c3 = fmaf(a, sf[bk + o3], c3);
        }
        int R = bi / 48, Cc = bi % 48;
        size_t base = (size_t)bc * HIR * HIR + (size_t)(R * 10) * HIR + Cc * 10;
        size_t i0 = base + (size_t)(q0 / 10) * HIR + q0 % 10;
        float x = out[i0]; out[i0] = fmaf(c0, x, x);
        size_t i1 = base + (size_t)(q1 / 10) * HIR + q1 % 10;
        x = out[i1]; out[i1] = fmaf(c1, x, x);
        size_t i2 = base + (size_t)(q2 / 10) * HIR + q2 % 10;
        x = out[i2]; out[i2] = fmaf(c2, x, x);
        if (has3) {
            size_t i3 = base + (size_t)(q3 / 10) * HIR + q3 % 10;
            x = out[i3]; out[i3] = fmaf(c3, x, x);
        }
        __syncwarp();
    }
}

// ======================= launch =======================
extern "C" void kernel_launch(void* const* d_in, const int* in_sizes, int n_in,
                              void* d_out, int out_size) {
    const float* feat   = (const float*)d_in[0];
    const float* attn   = (const float*)d_in[1];
    const float* w_psp  = (const float*)d_in[2];
    const float* b_psp0 = (const float*)d_in[3];
    const float* bpg    = (const float*)d_in[4];
    const float* bpb    = (const float*)d_in[5];
    const float* bpm    = (const float*)d_in[6];
    const float* bpv    = (const float*)d_in[7];
    const float* w_conv = (const float*)d_in[8];
    const float* bcg    = (const float*)d_in[9];
    const float* bcb    = (const float*)d_in[10];
    const float* bcm    = (const float*)d_in[11];
    const float* bcv    = (const float*)d_in[12];
    const float* wseg   = (const float*)d_in[13];
    const float* bseg   = (const float*)d_in[14];
    float* out = (float*)d_out;

    k_pool<<<NB * CINC, 128>>>(feat);
    k_branch<<<dim3(NB, 50), 128>>>(w_psp, b_psp0, bpg, bpb, bpm, bpv);
    k_Z<<<dim3(NB, 50), 256>>>(w_conv);
    k_gemm<<<dim3(57, 4, NB), 256>>>(w_conv, feat, bcg, bcb, bcm, bcv);
    k_conv3<<<dim3(60, 4, NB), 64>>>(wseg);
    k_segreduce<<<(NB * NC * SP + 255) / 256, 256>>>(bseg);
    k_up<<<dim3(60, 60, NB), 64>>>(out);
    k_corr<<<dim3(NB * NC, 18), 128>>>(attn, out);
    if (out_size >= XOUT_ELEMS + ATT_ELEMS) {
        cudaMemcpyAsync(out + XOUT_ELEMS, attn, (size_t)ATT_ELEMS * sizeof(float),
                        cudaMemcpyDeviceToDevice);
    }
}

// round 5
// speedup vs baseline: 1.7653x; 1.0842x over previous
#include <cuda_runtime.h>
#include <math.h>
#include <stdint.h>

// ---------------- problem constants ----------------
#define NB   8
#define CINC 512
#define SP   3600            // 60*60
#define NC   19
#define HIR  480

#define XOUT_ELEMS  35020800
#define ATT_ELEMS   12607488

// ---------------- scratch (device globals) ----------------
__device__ float g_pooled[NB * CINC * 50];
__device__ float g_ybr[NB * 128 * 50];
__device__ float g_Z[NB * CINC * 50];
__device__ float g_xmid[(size_t)NB * CINC * SP];
__device__ float g_seg[NB * NC * SP];
__device__ float g_seg4[4 * NB * NC * SP];   // conv3 channel-chunk partials
__device__ float g_feamap[NB * NC * SP];
__device__ float g_wT[512 * 9 * 20];         // transposed conv3 weights [c][tap][o(pad 20)]

__device__ __forceinline__ int branch_of(int j) {
    return (j == 0) ? 0 : (j < 5 ? 1 : (j < 14 ? 2 : 3));
}

// ======================= K0: transpose seg-conv weights =======================
__global__ void k_wT(const float* __restrict__ wseg) {
    int c = blockIdx.x;
    int t = threadIdx.x;            // 192
    if (t < 171) {
        int tap = t / 19, o = t % 19;
        g_wT[c * 180 + tap * 20 + o] = wseg[((size_t)o * 512 + c) * 9 + tap];
    }
    if (t < 9) g_wT[c * 180 + t * 20 + 19] = 0.f;
}

// ======================= K1: all 4 adaptive avg pools, no atomics =======================
__global__ void k_pool(const float* __restrict__ feat) {
    int bc = blockIdx.x;
    const float* src = feat + (size_t)bc * SP;
    __shared__ float seg[360];
    __shared__ float s6[36];
    int t = threadIdx.x;
    for (int i = t; i < 360; i += 128) {
        int row = i / 6, cs = i % 6;
        const float* p = src + row * 60 + cs * 10;
        float s = 0.f;
        #pragma unroll
        for (int j = 0; j < 10; j++) s += p[j];
        seg[i] = s;
    }
    __syncthreads();
    if (t < 36) {
        int r = t / 6, c = t % 6;
        float s = 0.f;
        #pragma unroll
        for (int rr = 0; rr < 10; rr++) s += seg[(r * 10 + rr) * 6 + c];
        s6[t] = s;
    }
    __syncthreads();
    float* P = g_pooled + (size_t)bc * 50;
    if (t < 36) P[14 + t] = s6[t] * (1.f / 100.f);
    if (t < 9) {
        int r = t / 3, c = t % 3;
        float s = s6[(2*r)*6 + 2*c] + s6[(2*r)*6 + 2*c+1]
                + s6[(2*r+1)*6 + 2*c] + s6[(2*r+1)*6 + 2*c+1];
        P[5 + t] = s * (1.f / 400.f);
    }
    if (t < 4) {
        int r = t / 2, c = t % 2;
        float s = 0.f;
        for (int rr = 0; rr < 3; rr++)
            for (int cc = 0; cc < 3; cc++) s += s6[(3*r+rr)*6 + 3*c+cc];
        P[1 + t] = s * (1.f / 900.f);
    }
    if (t == 0) {
        float s = 0.f;
        for (int i = 0; i < 36; i++) s += s6[i];
        P[0] = s * (1.f / 3600.f);
    }
}

// ======================= K2: branch 1x1 convs + bias/BN + relu =======================
__global__ void k_branch(const float* __restrict__ wpsp, const float* __restrict__ bpsp0,
                         const float* __restrict__ bg, const float* __restrict__ bb,
                         const float* __restrict__ bm, const float* __restrict__ bv) {
    int b = blockIdx.x, j = blockIdx.y;
    int i = branch_of(j);
    __shared__ float sp[512];
    for (int c = threadIdx.x; c < 512; c += 128)
        sp[c] = g_pooled[((size_t)b * 512 + c) * 50 + j];
    __syncthreads();
    int oc = threadIdx.x;
    const float* wr = wpsp + ((size_t)i * 128 + oc) * 512;
    float acc = 0.f;
    #pragma unroll 8
    for (int c = 0; c < 512; c++) acc = fmaf(wr[c], sp[c], acc);
    if (i == 0) {
        acc += bpsp0[oc];
    } else {
        int r = i - 1;
        float sc = bg[r*128 + oc] * rsqrtf(bv[r*128 + oc] + 1e-5f);
        acc = fmaf(acc - bm[r*128 + oc], sc, bb[r*128 + oc]);
    }
    g_ybr[((size_t)b * 128 + oc) * 50 + j] = fmaxf(acc, 0.f);
}

// ======================= K3: Z = Wconv[:, branch cols] @ y =======================
__global__ void k_Z(const float* __restrict__ wconv) {
    int b = blockIdx.x, j = blockIdx.y;
    int i = branch_of(j);
    __shared__ float sy[128];
    if (threadIdx.x < 128) sy[threadIdx.x] = g_ybr[((size_t)b * 128 + threadIdx.x) * 50 + j];
    __syncthreads();
    for (int oc = threadIdx.x; oc < 512; oc += blockDim.x) {
        const float* wr = wconv + (size_t)oc * 1024 + i * 128;
        float acc = 0.f;
        #pragma unroll 8
        for (int c = 0; c < 128; c++) acc = fmaf(wr[c], sy[c], acc);
        g_Z[((size_t)b * 512 + oc) * 50 + j] = acc;
    }
}

// ======================= K4: tf32 tensor-core GEMM (unchanged) ============
struct IW { int i0, i1, i2, i3; float w00, w01, w10, w11; };

__device__ __forceinline__ IW make_iw(int h, int w, int p, int base) {
    float ratio = (float)(p - 1) / 59.0f;
    float ry = (float)h * ratio;
    float rx = (float)w * ratio;
    int y0 = (int)floorf(ry), x0 = (int)floorf(rx);
    int y1 = min(y0 + 1, p - 1), x1 = min(x0 + 1, p - 1);
    float fy = ry - (float)y0, fx = rx - (float)x0;
    IW r;
    r.i0 = base + y0 * p + x0; r.i1 = base + y0 * p + x1;
    r.i2 = base + y1 * p + x0; r.i3 = base + y1 * p + x1;
    r.w00 = (1.f - fy) * (1.f - fx); r.w01 = (1.f - fy) * fx;
    r.w10 = fy * (1.f - fx);         r.w11 = fy * fx;
    return r;
}

__device__ __forceinline__ uint32_t f2tf32(float x) {
    uint32_t r;
    asm("cvt.rna.tf32.f32 %0, %1;" : "=r"(r) : "f"(x));
    return r;
}

#define SA_STRIDE 36
#define SB_STRIDE 72
__global__ void __launch_bounds__(256, 2)
k_gemm(const float* __restrict__ wconv, const float* __restrict__ feat,
       const float* __restrict__ bg, const float* __restrict__ bb,
       const float* __restrict__ bm, const float* __restrict__ bv) {
    int nt = blockIdx.x, mt = blockIdx.y, b = blockIdx.z;
    __shared__ float smem_f[128 * SA_STRIDE + 32 * SB_STRIDE];
    uint32_t* sAu = (uint32_t*)smem_f;
    uint32_t* sBu = (uint32_t*)(smem_f + 128 * SA_STRIDE);

    int tid = threadIdx.x;
    int lane = tid & 31, wid = tid >> 5;
    int gid = lane >> 2, tid4 = lane & 3;
    int warp_m = wid >> 2, warp_n = wid & 3;
    int m_base = warp_m * 64, n_base = warp_n * 16;

    float acc[4][2][4];
    #pragma unroll
    for (int mi = 0; mi < 4; mi++)
        #pragma unroll
        for (int ni = 0; ni < 2; ni++)
            #pragma unroll
            for (int r = 0; r < 4; r++) acc[mi][ni][r] = 0.f;

    const float* Bbase = feat + (size_t)b * CINC * SP;

    for (int kk = 0; kk < 512; kk += 32) {
        #pragma unroll
        for (int r = 0; r < 4; r++) {
            int idx = r * 256 + tid;
            int m = idx >> 3, k4 = idx & 7;
            const float4 v = *(const float4*)&wconv[((size_t)(mt * 128 + m)) * 1024 + 512 + kk + k4 * 4];
            uint32_t* d = &sAu[m * SA_STRIDE + k4 * 4];
            d[0] = f2tf32(v.x); d[1] = f2tf32(v.y); d[2] = f2tf32(v.z); d[3] = f2tf32(v.w);
        }
        #pragma unroll
        for (int r = 0; r < 2; r++) {
            int idx = r * 256 + tid;
            int k = idx >> 4, n4 = idx & 15;
            int s0 = nt * 64 + n4 * 4;
            float4 v = make_float4(0.f, 0.f, 0.f, 0.f);
            if (s0 < SP)
                v = *(const float4*)&Bbase[(size_t)(kk + k) * SP + s0];
            uint32_t* d = &sBu[k * SB_STRIDE + n4 * 4];
            d[0] = f2tf32(v.x); d[1] = f2tf32(v.y); d[2] = f2tf32(v.z); d[3] = f2tf32(v.w);
        }
        __syncthreads();

        #pragma unroll
        for (int k0 = 0; k0 < 32; k0 += 8) {
            uint32_t af[4][4], bf[2][2];
            #pragma unroll
            for (int mi = 0; mi < 4; mi++) {
                int r0 = (m_base + mi * 16 + gid) * SA_STRIDE;
                af[mi][0] = sAu[r0 + k0 + tid4];
                af[mi][1] = sAu[r0 + 8 * SA_STRIDE + k0 + tid4];
                af[mi][2] = sAu[r0 + k0 + tid4 + 4];
                af[mi][3] = sAu[r0 + 8 * SA_STRIDE + k0 + tid4 + 4];
            }
            #pragma unroll
            for (int ni = 0; ni < 2; ni++) {
                int c = n_base + ni * 8 + gid;
                bf[ni][0] = sBu[(k0 + tid4) * SB_STRIDE + c];
                bf[ni][1] = sBu[(k0 + tid4 + 4) * SB_STRIDE + c];
            }
            #pragma unroll
            for (int mi = 0; mi < 4; mi++)
                #pragma unroll
                for (int ni = 0; ni < 2; ni++)
                    asm volatile(
                        "mma.sync.aligned.m16n8k8.row.col.f32.tf32.tf32.f32 "
                        "{%0,%1,%2,%3}, {%4,%5,%6,%7}, {%8,%9}, {%0,%1,%2,%3};"
                        : "+f"(acc[mi][ni][0]), "+f"(acc[mi][ni][1]),
                          "+f"(acc[mi][ni][2]), "+f"(acc[mi][ni][3])
                        : "r"(af[mi][0]), "r"(af[mi][1]), "r"(af[mi][2]), "r"(af[mi][3]),
                          "r"(bf[ni][0]), "r"(bf[ni][1]));
        }
        __syncthreads();
    }

    float* sZ = smem_f;
    for (int idx = tid; idx < 128 * 50; idx += 256) {
        int row = idx / 50, j = idx % 50;
        sZ[row * 52 + j] = g_Z[((size_t)b * 512 + mt * 128 + row) * 50 + j];
    }
    __syncthreads();

    float scv[8], mbv8[8], btv[8];
    #pragma unroll
    for (int mi = 0; mi < 4; mi++)
        #pragma unroll
        for (int hf2 = 0; hf2 < 2; hf2++) {
            int oc = mt * 128 + m_base + mi * 16 + gid + hf2 * 8;
            int e = mi * 2 + hf2;
            scv[e] = bg[oc] * rsqrtf(bv[oc] + 1e-5f);
            mbv8[e] = bm[oc]; btv[e] = bb[oc];
        }

    #pragma unroll
    for (int u = 0; u < 4; u++) {
        int ni = u >> 1, j = u & 1;
        int s = nt * 64 + n_base + ni * 8 + tid4 * 2 + j;
        if (s >= SP) continue;
        int h = s / 60, w = s % 60;
        IW w2 = make_iw(h, w, 2, 1);
        IW w3 = make_iw(h, w, 3, 5);
        IW w6 = make_iw(h, w, 6, 14);
        #pragma unroll
        for (int mi = 0; mi < 4; mi++)
            #pragma unroll
            for (int hf2 = 0; hf2 < 2; hf2++) {
                int row = m_base + mi * 16 + gid + hf2 * 8;
                int oc = mt * 128 + row;
                const float* zr = &sZ[row * 52];
                float val = acc[mi][ni][hf2 * 2 + j] + zr[0];
                val += w2.w00 * zr[w2.i0] + w2.w01 * zr[w2.i1] + w2.w10 * zr[w2.i2] + w2.w11 * zr[w2.i3];
                val += w3.w00 * zr[w3.i0] + w3.w01 * zr[w3.i1] + w3.w10 * zr[w3.i2] + w3.w11 * zr[w3.i3];
                val += w6.w00 * zr[w6.i0] + w6.w01 * zr[w6.i1] + w6.w10 * zr[w6.i2] + w6.w11 * zr[w6.i3];
                int e = mi * 2 + hf2;
                val = fmaf(val - mbv8[e], scv[e], btv[e]);
                g_xmid[((size_t)b * 512 + oc) * SP + s] = fmaxf(val, 0.f);
            }
    }
}

// ======================= K5: 3x3 conv v2 — 2 rows/block, div-free fills ==============
__global__ void __launch_bounds__(128)
k_conv3(const float* __restrict__ dummy) {
    int h0 = blockIdx.x * 2;                   // output rows h0, h0+1
    int q = blockIdx.y, b = blockIdx.z;
    int t = threadIdx.x;                       // 128
    int w6 = t & 63;                           // fill column  (0..63; 0..61 used)
    int half = t >> 6;                         // 0/1
    __shared__ float sh[16][4][64];            // 4 input rows h0-1..h0+2
    __shared__ __align__(16) float shw[16 * 9 * 20];
    float4 acc[5];
    #pragma unroll
    for (int i = 0; i < 5; i++) acc[i] = make_float4(0.f, 0.f, 0.f, 0.f);

    int r = half;                              // output row offset for compute
    int w = w6;                                // output column for compute (w<60)
    const float* xb = g_xmid + (size_t)b * CINC * SP;
    bool wok = (w6 < 62);
    int ww = w6 - 1;
    bool win = wok && (ww >= 0) && (ww < 60);

    for (int cc = q * 128; cc < q * 128 + 128; cc += 16) {
        // halo fill: rows half*2, half*2+1 of the 4-row window
        #pragma unroll
        for (int c = 0; c < 16; c++) {
            const float* xc = xb + (size_t)(cc + c) * SP;
            #pragma unroll
            for (int k = 0; k < 2; k++) {
                int rowi = half * 2 + k;
                int hh = h0 - 1 + rowi;
                float v = 0.f;
                if (win && hh >= 0 && hh < 60) v = xc[hh * 60 + ww];
                if (wok) sh[c][rowi][w6] = v;
            }
        }
        // weight stage: contiguous float4 copy from pre-transposed g_wT
        {
            const float4* src = (const float4*)(g_wT + cc * 180);
            float4* dst = (float4*)shw;
            #pragma unroll
            for (int l = t; l < 720; l += 128) dst[l] = src[l];
        }
        __syncthreads();
        if (w < 60) {
            #pragma unroll 4
            for (int c = 0; c < 16; c++) {
                #pragma unroll
                for (int ky = 0; ky < 3; ky++) {
                    #pragma unroll
                    for (int kx = 0; kx < 3; kx++) {
                        float v = sh[c][r + ky][w + kx];
                        const float4* wp4 = (const float4*)&shw[(c * 9 + ky * 3 + kx) * 20];
                        #pragma unroll
                        for (int g2 = 0; g2 < 5; g2++) {
                            float4 wv = wp4[g2];
                            acc[g2].x = fmaf(v, wv.x, acc[g2].x);
                            acc[g2].y = fmaf(v, wv.y, acc[g2].y);
                            acc[g2].z = fmaf(v, wv.z, acc[g2].z);
                            acc[g2].w = fmaf(v, wv.w, acc[g2].w);
                        }
                    }
                }
            }
        }
        __syncthreads();
    }
    if (w < 60) {
        float* sb = g_seg4 + (size_t)(q * NB + b) * NC * SP + (h0 + r) * 60 + w;
        #pragma unroll
        for (int g2 = 0; g2 < 5; g2++) {
            int o = g2 * 4;
            sb[(size_t)o * SP] = acc[g2].x;
            if (o + 1 < 19) sb[(size_t)(o + 1) * SP] = acc[g2].y;
            if (o + 2 < 19) sb[(size_t)(o + 2) * SP] = acc[g2].z;
            if (o + 3 < 19) sb[(size_t)(o + 3) * SP] = acc[g2].w;
        }
    }
}

// deterministic reduce of the 4 channel-chunk partials + bias
__global__ void k_segreduce(const float* __restrict__ bseg) {
    int e = blockIdx.x * 256 + threadIdx.x;
    const int TOT = NB * NC * SP;
    if (e >= TOT) return;
    int o = (e / SP) % NC;
    float s = bseg[o];
    #pragma unroll
    for (int q = 0; q < 4; q++) s += g_seg4[(size_t)q * TOT + e];
    g_seg[e] = s;
}

// ====== K6: bilinear 60->480 + argmax + 8x8 one-hot pooling, coalesced ============
__global__ void __launch_bounds__(256)
k_up(float* __restrict__ out) {
    int wfg = blockIdx.x, hf = blockIdx.y, b = blockIdx.z;   // block = 32 wide x 8 high
    int t = threadIdx.x;
    int px = t & 31, py = t >> 5;
    int H = hf * 8 + py, W = wfg * 32 + px;
    float ry = (float)H * (59.0f / 479.0f);
    float rx = (float)W * (59.0f / 479.0f);
    int y0 = (int)floorf(ry), x0 = (int)floorf(rx);
    int y1 = min(y0 + 1, 59), x1 = min(x0 + 1, 59);
    float fy = ry - (float)y0, fx = rx - (float)x0;
    int r0 = y0 * 60 + x0, r0b = y0 * 60 + x1;
    int r1 = y1 * 60 + x0, r1b = y1 * 60 + x1;
    const float* sp = g_seg + (size_t)b * NC * SP;
    float* ob = out + ((size_t)b * NC * HIR + H) * HIR + W;
    float best = -3.4e38f; int bidx = 0;
    #pragma unroll 1
    for (int c = 0; c < NC; c++) {
        const float* p = sp + (size_t)c * SP;
        float top = fmaf(fx, p[r0b] - p[r0], p[r0]);
        float bot = fmaf(fx, p[r1b] - p[r1], p[r1]);
        float v = fmaf(fy, bot - top, top);
        ob[(size_t)c * HIR * HIR] = v;
        if (v > best) { best = v; bidx = c; }
    }
    __shared__ int cnt[4][NC];
    if (t < 4 * NC) cnt[t / NC][t % NC] = 0;
    __syncthreads();
    atomicAdd(&cnt[px >> 3][bidx], 1);
    __syncthreads();
    if (t < 4 * NC) {
        int sub = t / NC, c = t % NC;
        g_feamap[((size_t)(b * NC + c)) * SP + hf * 60 + wfg * 4 + sub]
            = (float)cnt[sub][c] * (1.f / 64.f);
    }
}

// ====== K7: unfold + attention matmul + fold + x = x*(1+corr) ============
__global__ void k_corr(const float* __restrict__ att, float* __restrict__ out) {
    int bc = blockIdx.x;
    int chunk = blockIdx.y;
    __shared__ __align__(16) float sf[SP];
    __shared__ float sa[4][36];
    {
        const float4* src = (const float4*)(g_feamap + (size_t)bc * SP);
        float4* dst = (float4*)sf;
        for (int l = threadIdx.x; l < SP / 4; l += 128) dst[l] = src[l];
    }
    __syncthreads();
    int warp = threadIdx.x >> 5, lane = threadIdx.x & 31;
    int q0 = lane, q1 = lane + 32, q2 = lane + 64, q3 = lane + 96;
    bool has3 = (q3 < 100);
    int o0 = (q0 / 10) * 60 + q0 % 10;
    int o1 = (q1 / 10) * 60 + q1 % 10;
    int o2 = (q2 / 10) * 60 + q2 % 10;
    int o3 = has3 ? (q3 / 10) * 60 + q3 % 10 : 0;

    for (int tt = 0; tt < 32; tt++) {
        int bi = chunk * 128 + warp * 32 + tt;
        const float* ar = att + ((size_t)bc * 2304 + bi) * 36;
        float v = ar[lane];
        float v2 = 0.f;
        int nz = (v != 0.f) ? 1 : 0;
        if (lane < 4) { v2 = ar[32 + lane]; nz += (v2 != 0.f) ? 1 : 0; }
        #pragma unroll
        for (int s = 16; s; s >>= 1) nz += __shfl_xor_sync(0xffffffffu, nz, s);
        float scale = 1.f / ((float)nz + 1e-5f);
        sa[warp][lane] = v * scale;
        if (lane < 4) sa[warp][32 + lane] = v2 * scale;
        __syncwarp();
        float c0 = 0.f, c1 = 0.f, c2 = 0.f, c3 = 0.f;
        #pragma unroll
        for (int k = 0; k < 36; k++) {
            int bk = (k / 6) * 600 + (k % 6) * 10;
            float a = sa[warp][k];
            c0 = fmaf(a, sf[bk + o0], c0);
            c1 = fmaf(a, sf[bk + o1], c1);
            c2 = fmaf(a, sf[bk + o2], c2);
            c3 = fmaf(a, sf[bk + o3], c3);
        }
        int R = bi / 48, Cc = bi % 48;
        size_t base = (size_t)bc * HIR * HIR + (size_t)(R * 10) * HIR + Cc * 10;
        size_t i0 = base + (size_t)(q0 / 10) * HIR + q0 % 10;
        float x = out[i0]; out[i0] = fmaf(c0, x, x);
        size_t i1 = base + (size_t)(q1 / 10) * HIR + q1 % 10;
        x = out[i1]; out[i1] = fmaf(c1, x, x);
        size_t i2 = base + (size_t)(q2 / 10) * HIR + q2 % 10;
        x = out[i2]; out[i2] = fmaf(c2, x, x);
        if (has3) {
            size_t i3 = base + (size_t)(q3 / 10) * HIR + q3 % 10;
            x = out[i3]; out[i3] = fmaf(c3, x, x);
        }
        __syncwarp();
    }
}

// ======================= launch =======================
extern "C" void kernel_launch(void* const* d_in, const int* in_sizes, int n_in,
                              void* d_out, int out_size) {
    const float* feat   = (const float*)d_in[0];
    const float* attn   = (const float*)d_in[1];
    const float* w_psp  = (const float*)d_in[2];
    const float* b_psp0 = (const float*)d_in[3];
    const float* bpg    = (const float*)d_in[4];
    const float* bpb    = (const float*)d_in[5];
    const float* bpm    = (const float*)d_in[6];
    const float* bpv    = (const float*)d_in[7];
    const float* w_conv = (const float*)d_in[8];
    const float* bcg    = (const float*)d_in[9];
    const float* bcb    = (const float*)d_in[10];
    const float* bcm    = (const float*)d_in[11];
    const float* bcv    = (const float*)d_in[12];
    const float* wseg   = (const float*)d_in[13];
    const float* bseg   = (const float*)d_in[14];
    float* out = (float*)d_out;

    k_wT<<<512, 192>>>(wseg);
    k_pool<<<NB * CINC, 128>>>(feat);
    k_branch<<<dim3(NB, 50), 128>>>(w_psp, b_psp0, bpg, bpb, bpm, bpv);
    k_Z<<<dim3(NB, 50), 256>>>(w_conv);
    k_gemm<<<dim3(57, 4, NB), 256>>>(w_conv, feat, bcg, bcb, bcm, bcv);
    k_conv3<<<dim3(30, 4, NB), 128>>>(nullptr);
    k_segreduce<<<(NB * NC * SP + 255) / 256, 256>>>(bseg);
    k_up<<<dim3(15, 60, NB), 256>>>(out);
    k_corr<<<dim3(NB * NC, 18), 128>>>(attn, out);
    if (out_size >= XOUT_ELEMS + ATT_ELEMS) {
        cudaMemcpyAsync(out + XOUT_ELEMS, attn, (size_t)ATT_ELEMS * sizeof(float),
                        cudaMemcpyDeviceToDevice);
    }
}